// round 2
// baseline (speedup 1.0000x reference)
#include <cuda_runtime.h>

#define FULL 0xFFFFFFFFu

__device__ __forceinline__ unsigned long long pack2(float a, float b) {
    unsigned long long r;
    asm("mov.b64 %0, {%1, %2};" : "=l"(r) : "f"(a), "f"(b));
    return r;
}
__device__ __forceinline__ void unpack2(unsigned long long p, float& a, float& b) {
    asm("mov.b64 {%0, %1}, %2;" : "=f"(a), "=f"(b) : "l"(p));
}
__device__ __forceinline__ unsigned long long fma2(unsigned long long a,
                                                   unsigned long long b,
                                                   unsigned long long c) {
    unsigned long long d;
    asm("fma.rn.f32x2 %0, %1, %2, %3;" : "=l"(d) : "l"(a), "l"(b), "l"(c));
    return d;
}
__device__ __forceinline__ unsigned long long add2(unsigned long long a,
                                                   unsigned long long b) {
    unsigned long long d;
    asm("add.rn.f32x2 %0, %1, %2;" : "=l"(d) : "l"(a), "l"(b));
    return d;
}

__device__ __forceinline__ float fast_sigmoid(float x) {
    return __fdividef(1.0f, 1.0f + __expf(-x));
}

// One CTA per batch. Threads 0..255: layer-0 LSTM (thread t owns gate column
// g*64+u, weights register-resident as f32x2 pairs). h broadcast from SMEM is
// loaded as ulonglong2 so each LDS.128 directly yields two f32x2 operands
// (no packing MOVs). Threads 256..287 (warp 8): layer-1 LSTM (units=1) +
// dense, one step lagged. One __syncthreads per step.
__global__ __launch_bounds__(288, 2)
void lstm_stack_kernel(const float* __restrict__ x,
                       const float* __restrict__ W0,
                       const float* __restrict__ b0,
                       const float* __restrict__ W1,
                       const float* __restrict__ b1,
                       const float* __restrict__ Wd,
                       const float* __restrict__ bd,
                       float* __restrict__ out)
{
    constexpr int T = 2048;

    const int bb   = blockIdx.x;
    const int tid  = threadIdx.x;
    const int lane = tid & 31;
    const int wid  = tid >> 5;

    __shared__ __align__(16) float x_sh[T];
    __shared__ __align__(16) float h_sh[2][64];
    __shared__ float red[9];
    __shared__ float inv_sh;

    // ---- Phase 0: load x tile, l2-normalize over time ----
    const float* xb = x + bb * T;
    float ps = 0.f;
    for (int i = tid; i < T; i += 288) {
        float v = xb[i];
        x_sh[i] = v;
        ps = fmaf(v, v, ps);
    }
    #pragma unroll
    for (int o = 16; o > 0; o >>= 1) ps += __shfl_xor_sync(FULL, ps, o);
    if (lane == 0) red[wid] = ps;
    if (tid < 64) h_sh[0][tid] = 0.f;   // h_{-1} = 0
    __syncthreads();
    if (tid == 0) {
        float s = 0.f;
        #pragma unroll
        for (int i = 0; i < 9; ++i) s += red[i];
        inv_sh = rsqrtf(fmaxf(s, 1e-12f));
    }
    __syncthreads();
    {
        float inv = inv_sh;
        for (int i = tid; i < T; i += 288) x_sh[i] *= inv;
    }
    // (ordered by the sync at the top of the main loop)

    // ---- Per-thread persistent state / weights ----
    const int g = tid & 3;      // gate: 0=i 1=j 2=f 3=o
    const int u = tid >> 2;     // unit 0..63
    unsigned long long wp[32];  // layer-0 column weights, packed f32x2
    float wx = 0.f, b0v = 0.f;
    float c0 = 0.f;

    // layer-1 (warp 8) state
    const int l1g  = lane & 3;
    const int l1bk = lane >> 2;
    float w1r[8];
    float w1h = 0.f, b1v = 0.f, wdv = 0.f, bdv = 0.f;
    float c1 = 0.f, h1 = 0.f;

    if (tid < 256) {
        const int col = g * 64 + u;
        wx  = W0[col];        // row 0: x weight
        b0v = b0[col];
        #pragma unroll
        for (int p = 0; p < 32; ++p) {
            float a  = W0[(1 + 2 * p) * 256 + col];
            float bv = W0[(2 + 2 * p) * 256 + col];
            wp[p] = pack2(a, bv);
        }
    } else {
        #pragma unroll
        for (int j = 0; j < 8; ++j)
            w1r[j] = W1[(l1bk + 8 * j) * 4 + l1g];
        w1h = W1[64 * 4 + l1g];
        b1v = b1[l1g];
        wdv = Wd[0];
        bdv = bd[0];
    }

    float* outb = out + bb * T;

    // ---- Main recurrence: t = 0..T. Layer-0 active for t<T, layer-1
    // processes step t-1 (so the final iteration drains layer-1). ----
    #pragma unroll 1
    for (int t = 0; t <= T; ++t) {
        __syncthreads();                 // h_sh[t&1] = h_{t-1} now valid
        const int cur = t & 1;
        if (tid < 256) {
            if (t < T) {
                float xt = x_sh[t];
                const ulonglong2* hp = (const ulonglong2*)h_sh[cur];
                // seed a0 with the x-path + bias (packed into the low lane)
                unsigned long long a0 = pack2(fmaf(xt, wx, b0v), 0.f);
                unsigned long long a1 = pack2(0.f, 0.f);
                unsigned long long a2 = a1, a3 = a1;
                #pragma unroll
                for (int i = 0; i < 16; ++i) {
                    ulonglong2 hv = hp[i];   // LDS.128 -> two packed f32x2
                    if (i & 1) { a2 = fma2(hv.x, wp[2*i], a2); a3 = fma2(hv.y, wp[2*i+1], a3); }
                    else       { a0 = fma2(hv.x, wp[2*i], a0); a1 = fma2(hv.y, wp[2*i+1], a1); }
                }
                unsigned long long s01 = add2(add2(a0, a1), add2(a2, a3));
                float slo, shi; unpack2(s01, slo, shi);
                float z = slo + shi;

                // branch-free gate nonlinearity: tanh(x) = 2*sigmoid(2x)-1
                float zz = (g == 2) ? (z + 1.0f) : z;   // forget bias
                float sv = (g == 1) ? (zz + zz) : zz;
                float sg = fast_sigmoid(sv);
                float r  = (g == 1) ? (2.f * sg - 1.f) : sg;

                float ri = __shfl_sync(FULL, r, 0, 4);
                float rj = __shfl_sync(FULL, r, 1, 4);
                float rf = __shfl_sync(FULL, r, 2, 4);
                float ro = __shfl_sync(FULL, r, 3, 4);
                c0 = fmaf(rf, c0, ri * rj);             // redundant in 4 lanes (bitwise identical)
                float th = 2.f * fast_sigmoid(c0 + c0) - 1.f;
                float h  = ro * th;
                if (g == 0) h_sh[cur ^ 1][u] = h;
            }
        } else {
            if (t >= 1) {
                // layer-1 for step s = t-1, input h_sh[cur] = h^{(0)}_{t-1}
                const float* hv = h_sh[cur];
                float p = 0.f;
                #pragma unroll
                for (int j = 0; j < 8; ++j)
                    p = fmaf(hv[l1bk + 8 * j], w1r[j], p);
                p += __shfl_xor_sync(FULL, p, 4);
                p += __shfl_xor_sync(FULL, p, 8);
                p += __shfl_xor_sync(FULL, p, 16);
                float z1 = fmaf(h1, w1h, p + b1v);

                float zz = (l1g == 2) ? (z1 + 1.0f) : z1;
                float sv = (l1g == 1) ? (zz + zz) : zz;
                float sg = fast_sigmoid(sv);
                float r  = (l1g == 1) ? (2.f * sg - 1.f) : sg;

                float ri = __shfl_sync(FULL, r, 0, 4);
                float rj = __shfl_sync(FULL, r, 1, 4);
                float rf = __shfl_sync(FULL, r, 2, 4);
                float ro = __shfl_sync(FULL, r, 3, 4);
                c1 = fmaf(rf, c1, ri * rj);
                float th = 2.f * fast_sigmoid(c1 + c1) - 1.f;
                h1 = ro * th;
                if (lane == 0) outb[t - 1] = fmaf(h1, wdv, bdv);
            }
        }
    }
}

extern "C" void kernel_launch(void* const* d_in, const int* in_sizes, int n_in,
                              void* d_out, int out_size) {
    const float* x  = (const float*)d_in[0];
    const float* W0 = (const float*)d_in[1];
    const float* b0 = (const float*)d_in[2];
    const float* W1 = (const float*)d_in[3];
    const float* b1 = (const float*)d_in[4];
    const float* Wd = (const float*)d_in[5];
    const float* bd = (const float*)d_in[6];
    float* out = (float*)d_out;
    lstm_stack_kernel<<<256, 288>>>(x, W0, b0, W1, b1, Wd, bd, out);
}

// round 3
// speedup vs baseline: 1.0353x; 1.0353x over previous
#include <cuda_runtime.h>

#define FULL 0xFFFFFFFFu

__device__ __forceinline__ unsigned long long pack2(float a, float b) {
    unsigned long long r;
    asm("mov.b64 %0, {%1, %2};" : "=l"(r) : "f"(a), "f"(b));
    return r;
}
__device__ __forceinline__ void unpack2(unsigned long long p, float& a, float& b) {
    asm("mov.b64 {%0, %1}, %2;" : "=f"(a), "=f"(b) : "l"(p));
}
__device__ __forceinline__ unsigned long long fma2(unsigned long long a,
                                                   unsigned long long b,
                                                   unsigned long long c) {
    unsigned long long d;
    asm("fma.rn.f32x2 %0, %1, %2, %3;" : "=l"(d) : "l"(a), "l"(b), "l"(c));
    return d;
}
__device__ __forceinline__ unsigned long long add2(unsigned long long a,
                                                   unsigned long long b) {
    unsigned long long d;
    asm("add.rn.f32x2 %0, %1, %2;" : "=l"(d) : "l"(a), "l"(b));
    return d;
}

__device__ __forceinline__ float fast_sigmoid(float x) {
    return __fdividef(1.0f, 1.0f + __expf(-x));
}

// One CTA per batch, 160 threads.
// Threads 0..127: layer-0 LSTM. Thread t = (unit u = t>>1, type = t&1).
//   type0 owns gate columns (i: u, j: 64+u); type1 owns (f: 128+u, o: 192+u).
//   Each thread loads the 64-wide h broadcast ONCE (16 LDS.128) and feeds two
//   register-resident weight columns (f32x2 packed). One shfl_xor(1) exchanges
//   sigma(f) <-> sigma(i)*tanh(j) inside the pair; both threads update c
//   identically; type1 computes and stores h. Forget bias folded into bias reg.
// Threads 128..159 (warp 4): layer-1 LSTM (units=1) + dense, one step lagged.
// One __syncthreads per step.
__global__ __launch_bounds__(160, 2)
void lstm_stack_kernel(const float* __restrict__ x,
                       const float* __restrict__ W0,
                       const float* __restrict__ b0,
                       const float* __restrict__ W1,
                       const float* __restrict__ b1,
                       const float* __restrict__ Wd,
                       const float* __restrict__ bd,
                       float* __restrict__ out)
{
    constexpr int T = 2048;

    const int bb   = blockIdx.x;
    const int tid  = threadIdx.x;
    const int lane = tid & 31;
    const int wid  = tid >> 5;

    __shared__ __align__(16) float x_sh[T];
    __shared__ __align__(16) float h_sh[2][64];
    __shared__ float red[5];
    __shared__ float inv_sh;

    // ---- Phase 0: load x tile, l2-normalize over time ----
    const float* xb = x + bb * T;
    float ps = 0.f;
    for (int i = tid; i < T; i += 160) {
        float v = xb[i];
        x_sh[i] = v;
        ps = fmaf(v, v, ps);
    }
    #pragma unroll
    for (int o = 16; o > 0; o >>= 1) ps += __shfl_xor_sync(FULL, ps, o);
    if (lane == 0) red[wid] = ps;
    if (tid < 64) h_sh[0][tid] = 0.f;   // h_{-1} = 0
    __syncthreads();
    if (tid == 0) {
        float s = 0.f;
        #pragma unroll
        for (int i = 0; i < 5; ++i) s += red[i];
        inv_sh = rsqrtf(fmaxf(s, 1e-12f));
    }
    __syncthreads();
    {
        float inv = inv_sh;
        for (int i = tid; i < T; i += 160) x_sh[i] *= inv;
    }
    // (ordered by the sync at the top of the main loop)

    // ---- Per-thread persistent state / weights ----
    const int u    = tid >> 1;
    const int type = tid & 1;           // 0: (i,j)   1: (f,o)
    unsigned long long wpa[32], wpb[32];
    float wxa = 0.f, wxb = 0.f, ba = 0.f, bb2 = 0.f;
    float c0 = 0.f;

    // layer-1 (warp 4) state
    const int l1g  = lane & 3;
    const int l1bk = lane >> 2;
    float w1r[8];
    float w1h = 0.f, b1v = 0.f, wdv = 0.f, bdv = 0.f;
    float c1 = 0.f, h1 = 0.f;

    if (tid < 128) {
        const int ca = u + (type ? 128 : 0);   // i or f column
        const int cb = ca + 64;                // j or o column
        wxa = W0[ca];
        wxb = W0[cb];
        ba  = b0[ca] + (type ? 1.0f : 0.0f);   // fold FORGET_BIAS
        bb2 = b0[cb];
        #pragma unroll
        for (int p = 0; p < 32; ++p) {
            wpa[p] = pack2(W0[(1 + 2 * p) * 256 + ca], W0[(2 + 2 * p) * 256 + ca]);
            wpb[p] = pack2(W0[(1 + 2 * p) * 256 + cb], W0[(2 + 2 * p) * 256 + cb]);
        }
    } else {
        #pragma unroll
        for (int j = 0; j < 8; ++j)
            w1r[j] = W1[(l1bk + 8 * j) * 4 + l1g];
        w1h = W1[64 * 4 + l1g];
        b1v = b1[l1g];
        wdv = Wd[0];
        bdv = bd[0];
    }

    float* outb = out + bb * T;

    // ---- Main recurrence: t = 0..T. Layer-0 active for t<T, layer-1
    // processes step t-1 (so the final iteration drains layer-1). ----
    #pragma unroll 1
    for (int t = 0; t <= T; ++t) {
        __syncthreads();                 // h_sh[t&1] = h_{t-1} now valid
        const int cur = t & 1;
        if (tid < 128) {
            if (t < T) {
                float xt = x_sh[t];
                const ulonglong2* hp = (const ulonglong2*)h_sh[cur];
                unsigned long long zero = pack2(0.f, 0.f);
                unsigned long long a0 = pack2(fmaf(xt, wxa, ba), 0.f);
                unsigned long long a1 = zero;
                unsigned long long e0 = pack2(fmaf(xt, wxb, bb2), 0.f);
                unsigned long long e1 = zero;
                #pragma unroll
                for (int i = 0; i < 16; ++i) {
                    ulonglong2 hv = hp[i];   // one LDS.128 feeds both gates
                    a0 = fma2(hv.x, wpa[2 * i],     a0);
                    a1 = fma2(hv.y, wpa[2 * i + 1], a1);
                    e0 = fma2(hv.x, wpb[2 * i],     e0);
                    e1 = fma2(hv.y, wpb[2 * i + 1], e1);
                }
                float za, zb;
                {
                    unsigned long long sa_ = add2(a0, a1);
                    unsigned long long sb_ = add2(e0, e1);
                    float lo, hi;
                    unpack2(sa_, lo, hi); za = lo + hi;
                    unpack2(sb_, lo, hi); zb = lo + hi;
                }

                // type0: sa = sigma(i), rb = tanh(j); send product.
                // type1: sa = sigma(f+1) (bias folded), sb = sigma(o); send sa.
                float sa  = fast_sigmoid(za);
                float zb2 = type ? zb : (zb + zb);
                float sb  = fast_sigmoid(zb2);
                float rb  = type ? sb : (2.f * sb - 1.f);   // tanh(j) on type0
                float send = type ? sa : (sa * rb);
                float recv = __shfl_xor_sync(FULL, send, 1);
                float fg  = type ? sa : recv;               // sigma(f+1)
                float inc = type ? recv : send;             // sigma(i)*tanh(j)
                c0 = fmaf(fg, c0, inc);                     // identical in pair
                float th = 2.f * fast_sigmoid(c0 + c0) - 1.f;
                float h  = rb * th;                         // valid on type1 (rb = sigma(o))
                if (type) h_sh[cur ^ 1][u] = h;
            }
        } else {
            if (t >= 1) {
                // layer-1 for step s = t-1, input h_sh[cur] = h^{(0)}_{t-1}
                const float* hv = h_sh[cur];
                float p = 0.f;
                #pragma unroll
                for (int j = 0; j < 8; ++j)
                    p = fmaf(hv[l1bk + 8 * j], w1r[j], p);
                p += __shfl_xor_sync(FULL, p, 4);
                p += __shfl_xor_sync(FULL, p, 8);
                p += __shfl_xor_sync(FULL, p, 16);
                float z1 = fmaf(h1, w1h, p + b1v);

                float zz = (l1g == 2) ? (z1 + 1.0f) : z1;
                float sv = (l1g == 1) ? (zz + zz) : zz;
                float sg = fast_sigmoid(sv);
                float r  = (l1g == 1) ? (2.f * sg - 1.f) : sg;

                float ri = __shfl_sync(FULL, r, 0, 4);
                float rj = __shfl_sync(FULL, r, 1, 4);
                float rf = __shfl_sync(FULL, r, 2, 4);
                float ro = __shfl_sync(FULL, r, 3, 4);
                c1 = fmaf(rf, c1, ri * rj);
                float th = 2.f * fast_sigmoid(c1 + c1) - 1.f;
                h1 = ro * th;
                if (lane == 0) outb[t - 1] = fmaf(h1, wdv, bdv);
            }
        }
    }
}

extern "C" void kernel_launch(void* const* d_in, const int* in_sizes, int n_in,
                              void* d_out, int out_size) {
    const float* x  = (const float*)d_in[0];
    const float* W0 = (const float*)d_in[1];
    const float* b0 = (const float*)d_in[2];
    const float* W1 = (const float*)d_in[3];
    const float* b1 = (const float*)d_in[4];
    const float* Wd = (const float*)d_in[5];
    const float* bd = (const float*)d_in[6];
    float* out = (float*)d_out;
    lstm_stack_kernel<<<256, 160>>>(x, W0, b0, W1, b1, Wd, bd, out);
}

// round 4
// speedup vs baseline: 1.2451x; 1.2027x over previous
#include <cuda_runtime.h>

#define FULL 0xFFFFFFFFu

__device__ __forceinline__ unsigned long long pack2(float a, float b) {
    unsigned long long r;
    asm("mov.b64 %0, {%1, %2};" : "=l"(r) : "f"(a), "f"(b));
    return r;
}
__device__ __forceinline__ void unpack2(unsigned long long p, float& a, float& b) {
    asm("mov.b64 {%0, %1}, %2;" : "=f"(a), "=f"(b) : "l"(p));
}
__device__ __forceinline__ unsigned long long fma2(unsigned long long a,
                                                   unsigned long long b,
                                                   unsigned long long c) {
    unsigned long long d;
    asm("fma.rn.f32x2 %0, %1, %2, %3;" : "=l"(d) : "l"(a), "l"(b), "l"(c));
    return d;
}
__device__ __forceinline__ unsigned long long add2(unsigned long long a,
                                                   unsigned long long b) {
    unsigned long long d;
    asm("add.rn.f32x2 %0, %1, %2;" : "=l"(d) : "l"(a), "l"(b));
    return d;
}

__device__ __forceinline__ float fast_sigmoid(float x) {
    return __fdividef(1.0f, 1.0f + __expf(-x));
}

// One CTA per TWO batches, 160 threads, grid 128 (one CTA per SM, single wave).
// Threads 0..127: layer-0. Thread = (unit u = t>>1, type = t&1); type0 owns
// gate columns (i,j), type1 owns (f,o). Weights are batch-independent, so the
// same 64 f32x2 weight registers feed BOTH batches; the two batches' dot
// products and nonlinear tails run as independent ILP chains inside the
// thread, hiding the serial latency that bound round 3.
// Threads 128..159 (warp 4): layer-1 (units=1) + dense for both batches
// (lane halves 0-15 / 16-31), one step lagged. One __syncthreads per step.
__global__ __launch_bounds__(160, 1)
void lstm_stack_kernel(const float* __restrict__ x,
                       const float* __restrict__ W0,
                       const float* __restrict__ b0,
                       const float* __restrict__ W1,
                       const float* __restrict__ b1,
                       const float* __restrict__ Wd,
                       const float* __restrict__ bd,
                       float* __restrict__ out)
{
    constexpr int T = 2048;

    const int bb   = blockIdx.x;      // batch pair
    const int tid  = threadIdx.x;
    const int lane = tid & 31;
    const int wid  = tid >> 5;

    __shared__ __align__(16) float x_sh[2][T];
    __shared__ __align__(16) float h_sh[2][2][64];   // [buffer][batch][unit]
    __shared__ float red[5];
    __shared__ float inv_sh[2];

    // ---- Phase 0: load both x tiles, l2-normalize over time ----
    for (int bi = 0; bi < 2; ++bi) {
        const float* xb = x + (2 * bb + bi) * T;
        float ps = 0.f;
        for (int i = tid; i < T; i += 160) {
            float v = xb[i];
            x_sh[bi][i] = v;
            ps = fmaf(v, v, ps);
        }
        #pragma unroll
        for (int o = 16; o > 0; o >>= 1) ps += __shfl_xor_sync(FULL, ps, o);
        if (lane == 0) red[wid] = ps;
        __syncthreads();
        if (tid == 0) {
            float s = 0.f;
            #pragma unroll
            for (int i = 0; i < 5; ++i) s += red[i];
            inv_sh[bi] = rsqrtf(fmaxf(s, 1e-12f));
        }
        __syncthreads();               // also protects red[] reuse
    }
    {
        float i0 = inv_sh[0], i1 = inv_sh[1];
        for (int i = tid; i < T; i += 160) {
            x_sh[0][i] *= i0;
            x_sh[1][i] *= i1;
        }
    }
    if (tid < 128) ((float*)h_sh[0])[tid] = 0.f;   // h_{-1} = 0, both batches
    // (ordered by the sync at the top of the main loop)

    // ---- Per-thread persistent state / weights ----
    const int u    = tid >> 1;
    const int type = tid & 1;           // 0: (i,j)   1: (f,o)
    unsigned long long wpa[32], wpb[32];
    float wxa = 0.f, wxb = 0.f, ba = 0.f, bb2 = 0.f;
    float c0_0 = 0.f, c0_1 = 0.f;

    // layer-1 (warp 4) state: lanes 0-15 -> batch0, 16-31 -> batch1
    const int l1b  = lane >> 4;         // batch half
    const int l1g  = lane & 3;
    const int l1bk = (lane >> 2) & 3;   // bank 0..3 within the 16-lane half
    float w1r[16];
    float w1h = 0.f, b1v = 0.f, wdv = 0.f, bdv = 0.f;
    float c1 = 0.f, h1 = 0.f;

    if (tid < 128) {
        const int ca = u + (type ? 128 : 0);   // i or f column
        const int cb = ca + 64;                // j or o column
        wxa = W0[ca];
        wxb = W0[cb];
        ba  = b0[ca] + (type ? 1.0f : 0.0f);   // fold FORGET_BIAS
        bb2 = b0[cb];
        #pragma unroll
        for (int p = 0; p < 32; ++p) {
            wpa[p] = pack2(W0[(1 + 2 * p) * 256 + ca], W0[(2 + 2 * p) * 256 + ca]);
            wpb[p] = pack2(W0[(1 + 2 * p) * 256 + cb], W0[(2 + 2 * p) * 256 + cb]);
        }
    } else {
        #pragma unroll
        for (int j = 0; j < 16; ++j)
            w1r[j] = W1[(l1bk + 4 * j) * 4 + l1g];
        w1h = W1[64 * 4 + l1g];
        b1v = b1[l1g];
        wdv = Wd[0];
        bdv = bd[0];
    }

    // ---- Main recurrence: t = 0..T. Layer-0 active for t<T, layer-1
    // processes step t-1 (final iteration drains layer-1). ----
    #pragma unroll 1
    for (int t = 0; t <= T; ++t) {
        __syncthreads();                 // h_sh[t&1] = h_{t-1} now valid
        const int cur = t & 1;
        if (tid < 128) {
            if (t < T) {
                float xt0 = x_sh[0][t], xt1 = x_sh[1][t];
                const ulonglong2* hp0 = (const ulonglong2*)h_sh[cur][0];
                const ulonglong2* hp1 = (const ulonglong2*)h_sh[cur][1];
                unsigned long long zero = pack2(0.f, 0.f);
                unsigned long long a00 = pack2(fmaf(xt0, wxa, ba), 0.f), a10 = zero;
                unsigned long long e00 = pack2(fmaf(xt0, wxb, bb2), 0.f), e10 = zero;
                unsigned long long a01 = pack2(fmaf(xt1, wxa, ba), 0.f), a11 = zero;
                unsigned long long e01 = pack2(fmaf(xt1, wxb, bb2), 0.f), e11 = zero;
                #pragma unroll
                for (int i = 0; i < 16; ++i) {
                    ulonglong2 hv0 = hp0[i];
                    ulonglong2 hv1 = hp1[i];
                    a00 = fma2(hv0.x, wpa[2 * i],     a00);
                    a10 = fma2(hv0.y, wpa[2 * i + 1], a10);
                    e00 = fma2(hv0.x, wpb[2 * i],     e00);
                    e10 = fma2(hv0.y, wpb[2 * i + 1], e10);
                    a01 = fma2(hv1.x, wpa[2 * i],     a01);
                    a11 = fma2(hv1.y, wpa[2 * i + 1], a11);
                    e01 = fma2(hv1.x, wpb[2 * i],     e01);
                    e11 = fma2(hv1.y, wpb[2 * i + 1], e11);
                }
                float za0, zb0, za1, zb1;
                {
                    float lo, hi;
                    unpack2(add2(a00, a10), lo, hi); za0 = lo + hi;
                    unpack2(add2(e00, e10), lo, hi); zb0 = lo + hi;
                    unpack2(add2(a01, a11), lo, hi); za1 = lo + hi;
                    unpack2(add2(e01, e11), lo, hi); zb1 = lo + hi;
                }

                // type0: sa = sigma(i), rb = tanh(j); sends sa*rb.
                // type1: sa = sigma(f+1), rb = sigma(o); sends sa.
                float sa0 = fast_sigmoid(za0);
                float sa1 = fast_sigmoid(za1);
                float sb0 = fast_sigmoid(type ? zb0 : (zb0 + zb0));
                float sb1 = fast_sigmoid(type ? zb1 : (zb1 + zb1));
                float rb0 = type ? sb0 : (2.f * sb0 - 1.f);
                float rb1 = type ? sb1 : (2.f * sb1 - 1.f);
                float send0 = type ? sa0 : (sa0 * rb0);
                float send1 = type ? sa1 : (sa1 * rb1);
                float recv0 = __shfl_xor_sync(FULL, send0, 1);
                float recv1 = __shfl_xor_sync(FULL, send1, 1);
                float fg0  = type ? sa0 : recv0;
                float inc0 = type ? recv0 : send0;
                float fg1  = type ? sa1 : recv1;
                float inc1 = type ? recv1 : send1;
                c0_0 = fmaf(fg0, c0_0, inc0);
                c0_1 = fmaf(fg1, c0_1, inc1);
                float th0 = 2.f * fast_sigmoid(c0_0 + c0_0) - 1.f;
                float th1 = 2.f * fast_sigmoid(c0_1 + c0_1) - 1.f;
                float h0 = rb0 * th0;     // valid on type1 (rb = sigma(o))
                float h1v = rb1 * th1;
                if (type) {
                    h_sh[cur ^ 1][0][u] = h0;
                    h_sh[cur ^ 1][1][u] = h1v;
                }
            }
        } else {
            if (t >= 1) {
                // layer-1 for step s = t-1, input h_sh[cur][l1b]
                const float* hv = h_sh[cur][l1b];
                float p = 0.f;
                #pragma unroll
                for (int j = 0; j < 16; ++j)
                    p = fmaf(hv[l1bk + 4 * j], w1r[j], p);
                p += __shfl_xor_sync(FULL, p, 4);    // stays within 16-lane half
                p += __shfl_xor_sync(FULL, p, 8);
                float z1 = fmaf(h1, w1h, p + b1v);

                float zz = (l1g == 2) ? (z1 + 1.0f) : z1;
                float sv = (l1g == 1) ? (zz + zz) : zz;
                float sg = fast_sigmoid(sv);
                float r  = (l1g == 1) ? (2.f * sg - 1.f) : sg;

                float ri = __shfl_sync(FULL, r, 0, 4);
                float rj = __shfl_sync(FULL, r, 1, 4);
                float rf = __shfl_sync(FULL, r, 2, 4);
                float ro = __shfl_sync(FULL, r, 3, 4);
                c1 = fmaf(rf, c1, ri * rj);
                float th = 2.f * fast_sigmoid(c1 + c1) - 1.f;
                h1 = ro * th;
                if ((lane & 15) == 0)
                    out[(2 * bb + l1b) * T + (t - 1)] = fmaf(h1, wdv, bdv);
            }
        }
    }
}

extern "C" void kernel_launch(void* const* d_in, const int* in_sizes, int n_in,
                              void* d_out, int out_size) {
    const float* x  = (const float*)d_in[0];
    const float* W0 = (const float*)d_in[1];
    const float* b0 = (const float*)d_in[2];
    const float* W1 = (const float*)d_in[3];
    const float* b1 = (const float*)d_in[4];
    const float* Wd = (const float*)d_in[5];
    const float* bd = (const float*)d_in[6];
    float* out = (float*)d_out;
    lstm_stack_kernel<<<128, 160>>>(x, W0, b0, W1, b1, Wd, bd, out);
}